// round 7
// baseline (speedup 1.0000x reference)
#include <cuda_runtime.h>
#include <cuda_bf16.h>

// ---------------- problem constants (fixed by the dataset) ----------------
#define NN      100000      // total nodes
#define HH      64          // hidden features
#define EE      800000      // edges per edge set
#define GG      50000       // ground nodes (ground_node = arange(N) < G)
#define NGRAPH  128
#define FIN     32
#define NBUK    21          // degree buckets 0..20 (bucket 0 <=> deg==0 <=> passthrough)
#define NPB     64          // nodes per apply-GEMM block
#define CHUNKS  ((NN + NPB - 1) / NPB)
#define LN_EPS  1e-5f

// ---------------- scratch (static device globals; no allocation) ----------
__device__ float g_h  [NN * HH];
__device__ float g_h0 [NN * HH];
__device__ float g_hs [NN * HH];
__device__ int   g_deg[NN];
__device__ int   g_cnt[NBUK];
__device__ int   g_off[NBUK];
__device__ int   g_cur[NBUK];
__device__ int   g_nb [NN];
__device__ int   g_list[NN];
__device__ float g_pooled[NGRAPH * HH];

// vector f32 reduction (PTX ISA 8.1+, sm_90+): 1 L2 atomic op for 16B
__device__ __forceinline__ void red_add_v4(float* p, float4 v) {
    asm volatile("red.global.add.v4.f32 [%0], {%1, %2, %3, %4};"
                 :: "l"(p), "f"(v.x), "f"(v.y), "f"(v.z), "f"(v.w) : "memory");
}

// ---------------- K1: embedding  h = x @ emb_w + emb_b ; h0 = h ----------
__global__ void k_embed(const float* __restrict__ x,
                        const float* __restrict__ w,
                        const float* __restrict__ b) {
    __shared__ float sw[FIN * HH];   // 8KB
    __shared__ float sb[HH];
    for (int i = threadIdx.x; i < FIN * HH; i += 256) sw[i] = w[i];
    if (threadIdx.x < HH) sb[threadIdx.x] = b[threadIdx.x];
    __syncthreads();

    int n = blockIdx.x * 256 + threadIdx.x;
    if (n >= NN) return;

    float xv[FIN];
    const float4* xp = reinterpret_cast<const float4*>(x + n * FIN);
#pragma unroll
    for (int q = 0; q < FIN / 4; q++) {
        float4 v = xp[q];
        xv[q*4+0] = v.x; xv[q*4+1] = v.y; xv[q*4+2] = v.z; xv[q*4+3] = v.w;
    }

#pragma unroll
    for (int cc = 0; cc < 4; cc++) {         // 4 chunks of 16 outputs
        float acc[16];
#pragma unroll
        for (int c = 0; c < 16; c++) acc[c] = sb[cc*16 + c];
#pragma unroll
        for (int k = 0; k < FIN; k++) {
            float xk = xv[k];
#pragma unroll
            for (int c = 0; c < 16; c++) acc[c] += xk * sw[k*HH + cc*16 + c];
        }
        float4* ho  = reinterpret_cast<float4*>(g_h  + n*HH + cc*16);
        float4* h0o = reinterpret_cast<float4*>(g_h0 + n*HH + cc*16);
#pragma unroll
        for (int q = 0; q < 4; q++) {
            float4 v = make_float4(acc[q*4], acc[q*4+1], acc[q*4+2], acc[q*4+3]);
            ho[q] = v; h0o[q] = v;
        }
    }
}

// ---------------- K2: scatter  hs[dst] += h[src] ; deg[dst]++ ------------
// 16 lanes per edge, one float4 per lane (contiguous 256B gather per edge)
__global__ void k_scatter(const int* __restrict__ src, const int* __restrict__ dst) {
    int t = blockIdx.x * 256 + threadIdx.x;
    int e = t >> 4;
    if (e >= EE) return;
    int c = t & 15;
    int s = src[e];
    int d = dst[e];
    if (c == 0) atomicAdd(&g_deg[d], 1);
    float4 v = *reinterpret_cast<const float4*>(&g_h[s * HH + c * 4]);
    red_add_v4(&g_hs[d * HH + c * 4], v);
}

// ---------------- K3: bucket assign + histogram ---------------------------
__global__ void k_bucket() {
    __shared__ int scnt[NBUK];
    int t = threadIdx.x;
    if (t < NBUK) scnt[t] = 0;
    __syncthreads();
    int i = blockIdx.x * 256 + t;
    int b = -1;
    if (i < NN) {
        int deg = g_deg[i];
        b = deg < NBUK - 1 ? deg : NBUK - 1;   // min(deg,20); 0 <=> passthrough
        g_nb[i] = b;
        atomicAdd(&scnt[b], 1);
    }
    __syncthreads();
    if (t < NBUK && scnt[t] > 0) atomicAdd(&g_cnt[t], scnt[t]);
}

// ---------------- K4: tiny exclusive scan + cursor reset ------------------
__global__ void k_scan() {
    if (threadIdx.x == 0) {
        int run = 0;
        for (int b = 0; b < NBUK; b++) { g_off[b] = run; run += g_cnt[b]; g_cur[b] = 0; }
    }
}

// ---------------- K5: fill bucketed node lists ----------------------------
__global__ void k_fill() {
    __shared__ int scnt[NBUK], sbase[NBUK], scur[NBUK];
    int t = threadIdx.x;
    if (t < NBUK) { scnt[t] = 0; scur[t] = 0; }
    __syncthreads();
    int i = blockIdx.x * 256 + t;
    int b = -1;
    if (i < NN) { b = g_nb[i]; atomicAdd(&scnt[b], 1); }
    __syncthreads();
    if (t < NBUK && scnt[t] > 0) sbase[t] = atomicAdd(&g_cur[t], scnt[t]);
    __syncthreads();
    if (i < NN) {
        int pos = atomicAdd(&scur[b], 1);
        g_list[g_off[b] + sbase[b] + pos] = i;
    }
}

// ---------------- K6: bucketed apply (batched GEMM per degree bucket) -----
// out = hs @ wl[d] + h @ wr[d] + bl[d]; bucket 0 passthrough (+optional relu)
// grid = (CHUNKS, NBUK), 256 threads, dynamic smem:
//   sWL[4096] sWR[4096] sA[4096] sB[4096] sBL[64]  -> 65792 bytes
#define APPLY_SMEM ((4096 * 4 + 64) * 4)

__global__ void k_apply(const float* __restrict__ wl_base,
                        const float* __restrict__ bl_base,
                        const float* __restrict__ wr_base,
                        int relu) {
    int b = blockIdx.y;
    int cnt = g_cnt[b];
    int chunk0 = blockIdx.x * NPB;
    if (chunk0 >= cnt) return;
    const int* list = g_list + g_off[b] + chunk0;
    int nvalid = cnt - chunk0; if (nvalid > NPB) nvalid = NPB;
    int tid = threadIdx.x;

    if (b == 0) {                       // deg==0: h unchanged, relu still applies
        if (!relu) return;
        for (int idx = tid; idx < nvalid * 16; idx += 256) {
            int n = list[idx >> 4];
            int c = (idx & 15) * 4;
            float4* p = reinterpret_cast<float4*>(&g_h[n * HH + c]);
            float4 v = *p;
            v.x = fmaxf(v.x, 0.f); v.y = fmaxf(v.y, 0.f);
            v.z = fmaxf(v.z, 0.f); v.w = fmaxf(v.w, 0.f);
            *p = v;
        }
        return;
    }

    extern __shared__ float smem[];
    float* sWL = smem;
    float* sWR = smem + 4096;
    float* sA  = smem + 8192;   // hs^T: [k][m]
    float* sB  = smem + 12288;  // h^T : [k][m]
    float* sBL = smem + 16384;

    const float* wl = wl_base + b * HH * HH;
    const float* wr = wr_base + b * HH * HH;
    const float* bl = bl_base + b * HH;

    for (int i = tid; i < 1024; i += 256) {
        reinterpret_cast<float4*>(sWL)[i] = reinterpret_cast<const float4*>(wl)[i];
        reinterpret_cast<float4*>(sWR)[i] = reinterpret_cast<const float4*>(wr)[i];
    }
    if (tid < HH) sBL[tid] = bl[tid];

    // stage activations transposed: sA[k][m] = hs[node_m][k]
    {
        int m  = tid & 63;
        int kq = tid >> 6;                 // 0..3, each covers 16 k's
        int node = (m < nvalid) ? list[m] : -1;
#pragma unroll
        for (int q = 0; q < 4; q++) {
            int k0 = kq * 16 + q * 4;
            float4 va = make_float4(0.f, 0.f, 0.f, 0.f), vb = va;
            if (node >= 0) {
                va = *reinterpret_cast<const float4*>(&g_hs[node * HH + k0]);
                vb = *reinterpret_cast<const float4*>(&g_h [node * HH + k0]);
            }
            sA[(k0+0)*64 + m] = va.x; sA[(k0+1)*64 + m] = va.y;
            sA[(k0+2)*64 + m] = va.z; sA[(k0+3)*64 + m] = va.w;
            sB[(k0+0)*64 + m] = vb.x; sB[(k0+1)*64 + m] = vb.y;
            sB[(k0+2)*64 + m] = vb.z; sB[(k0+3)*64 + m] = vb.w;
        }
    }
    __syncthreads();

    int tx4 = (tid & 15) * 4;   // output cols
    int ty4 = (tid >> 4) * 4;   // nodes
    float acc[4][4];
#pragma unroll
    for (int i = 0; i < 4; i++)
#pragma unroll
        for (int j = 0; j < 4; j++) acc[i][j] = sBL[tx4 + j];

#pragma unroll 8
    for (int k = 0; k < HH; k++) {
        float4 a  = *reinterpret_cast<const float4*>(&sA [k*64 + ty4]);
        float4 hh = *reinterpret_cast<const float4*>(&sB [k*64 + ty4]);
        float4 wl4 = *reinterpret_cast<const float4*>(&sWL[k*64 + tx4]);
        float4 wr4 = *reinterpret_cast<const float4*>(&sWR[k*64 + tx4]);
        float av[4] = {a.x, a.y, a.z, a.w};
        float hv[4] = {hh.x, hh.y, hh.z, hh.w};
        float lv[4] = {wl4.x, wl4.y, wl4.z, wl4.w};
        float rv[4] = {wr4.x, wr4.y, wr4.z, wr4.w};
#pragma unroll
        for (int i = 0; i < 4; i++)
#pragma unroll
            for (int j = 0; j < 4; j++)
                acc[i][j] += av[i] * lv[j] + hv[i] * rv[j];
    }

#pragma unroll
    for (int i = 0; i < 4; i++) {
        int m = (tid >> 4) * 4 + i;
        if (m < nvalid) {
            int node = list[m];
            float4 o = make_float4(acc[i][0], acc[i][1], acc[i][2], acc[i][3]);
            if (relu) {
                o.x = fmaxf(o.x, 0.f); o.y = fmaxf(o.y, 0.f);
                o.z = fmaxf(o.z, 0.f); o.w = fmaxf(o.w, 0.f);
            }
            *reinterpret_cast<float4*>(&g_h[node * HH + tx4]) = o;
        }
    }
}

// ---------------- K7: LayerNorm + residual --------------------------------
__global__ void k_ln(const float* __restrict__ g, const float* __restrict__ bb) {
    int wid = (blockIdx.x * 256 + threadIdx.x) >> 5;
    int lane = threadIdx.x & 31;
    if (wid >= NN) return;
    const float* hp = g_h + wid * HH;
    float v0 = hp[lane], v1 = hp[lane + 32];
    float s = v0 + v1;
#pragma unroll
    for (int o = 16; o > 0; o >>= 1) s += __shfl_xor_sync(0xffffffffu, s, o);
    float mu = s * (1.f / 64.f);
    float d0 = v0 - mu, d1 = v1 - mu;
    float q = d0 * d0 + d1 * d1;
#pragma unroll
    for (int o = 16; o > 0; o >>= 1) q += __shfl_xor_sync(0xffffffffu, q, o);
    float rstd = rsqrtf(q * (1.f / 64.f) + LN_EPS);
    const float* h0p = g_h0 + wid * HH;
    g_h[wid*HH + lane]      = d0 * rstd * g[lane]      + bb[lane]      + h0p[lane];
    g_h[wid*HH + lane + 32] = d1 * rstd * g[lane + 32] + bb[lane + 32] + h0p[lane + 32];
}

// ---------------- K8: pooled[batch[i]] += h[i] for ground nodes (i<G) -----
__global__ void k_pool(const int* __restrict__ batch_idx) {
    int t = blockIdx.x * 256 + threadIdx.x;
    int i = t >> 4;
    if (i >= GG) return;
    int c = (t & 15) * 4;
    int gidx = batch_idx[i];
    float4 v = *reinterpret_cast<const float4*>(&g_h[i * HH + c]);
    red_add_v4(&g_pooled[gidx * HH + c], v);
}

// ---------------- K9: out = pooled @ out_w + out_b ------------------------
__global__ void k_out(const float* __restrict__ ow, const float* __restrict__ ob,
                      float* __restrict__ out) {
    int gidx = threadIdx.x;           // 128 threads
    float acc = ob[0];
#pragma unroll
    for (int k = 0; k < HH; k++) acc += g_pooled[gidx * HH + k] * ow[k];
    out[gidx] = acc;
}

// ---------------- host launcher ------------------------------------------
extern "C" void kernel_launch(void* const* d_in, const int* in_sizes, int n_in,
                              void* d_out, int out_size) {
    (void)in_sizes; (void)n_in; (void)out_size;
    const float* x        = (const float*)d_in[0];
    // reference edge-set order: edge_index, node_subnode, subgraph_edge, subnode_node
    const int* eis[4] = { (const int*)d_in[1], (const int*)d_in[3],
                          (const int*)d_in[2], (const int*)d_in[4] };
    const int*   batch_idx = (const int*)d_in[7];
    const float* emb_w  = (const float*)d_in[8];
    const float* emb_b  = (const float*)d_in[9];
    const float* conv_wl = (const float*)d_in[10];
    const float* conv_bl = (const float*)d_in[11];
    const float* conv_wr = (const float*)d_in[12];
    const float* ln_g   = (const float*)d_in[13];
    const float* ln_b   = (const float*)d_in[14];
    const float* out_w  = (const float*)d_in[15];
    const float* out_b  = (const float*)d_in[16];
    float* out = (float*)d_out;

    void *p_hs, *p_deg, *p_cnt, *p_pooled;
    cudaGetSymbolAddress(&p_hs, g_hs);
    cudaGetSymbolAddress(&p_deg, g_deg);
    cudaGetSymbolAddress(&p_cnt, g_cnt);
    cudaGetSymbolAddress(&p_pooled, g_pooled);

    cudaFuncSetAttribute(k_apply, cudaFuncAttributeMaxDynamicSharedMemorySize,
                         APPLY_SMEM);

    k_embed<<<(NN + 255) / 256, 256>>>(x, emb_w, emb_b);

    for (int j = 0; j < 4; j++) {
        cudaMemsetAsync(p_hs, 0, sizeof(float) * NN * HH);
        cudaMemsetAsync(p_deg, 0, sizeof(int) * NN);
        cudaMemsetAsync(p_cnt, 0, sizeof(int) * NBUK);
        k_scatter<<<(EE * 16 + 255) / 256, 256>>>(eis[j], eis[j] + EE);
        k_bucket<<<(NN + 255) / 256, 256>>>();
        k_scan<<<1, 32>>>();
        k_fill<<<(NN + 255) / 256, 256>>>();
        dim3 grid(CHUNKS, NBUK);
        k_apply<<<grid, 256, APPLY_SMEM>>>(conv_wl + j * NBUK * HH * HH,
                                           conv_bl + j * NBUK * HH,
                                           conv_wr + j * NBUK * HH * HH,
                                           (j < 3) ? 1 : 0);
    }

    k_ln<<<(NN * 32 + 255) / 256, 256>>>(ln_g, ln_b);

    cudaMemsetAsync(p_pooled, 0, sizeof(float) * NGRAPH * HH);
    k_pool<<<(GG * 16 + 255) / 256, 256>>>(batch_idx);
    k_out<<<1, NGRAPH>>>(out_w, out_b, out);
}